// round 13
// baseline (speedup 1.0000x reference)
#include <cuda_runtime.h>
#include <cuda_bf16.h>
#include <cuda_fp16.h>
#include <cstdint>

#define NCTX 4096
#define DM   512
#define NB   2
#define LDKT (NB*NCTX)

// Scratch
__device__ __nv_bfloat16 g_xhi[(size_t)NB*NCTX*DM];
__device__ __nv_bfloat16 g_xlo[(size_t)NB*NCTX*DM];
__device__ __nv_bfloat16 g_Whi[(size_t)DM*DM];
__device__ __nv_bfloat16 g_Wlo[(size_t)DM*DM];
__device__ __nv_bfloat16 g_Khi[(size_t)NB*NCTX*DM];
__device__ __nv_bfloat16 g_Klo[(size_t)NB*NCTX*DM];
__device__ __half        g_Ktb[(size_t)DM*NB*NCTX];   // fp16 K^T
__device__ float         g_S  [(size_t)NB*NCTX*NCTX]; // fp32 scores
__device__ __half        g_Pb [(size_t)NB*NCTX*NCTX]; // fp16 exp(s-m)
__device__ float         g_inv[(size_t)NB*NCTX];      // 1 / rowsum(exp)

// ---------------------------------------------------------------------------
// helpers
// ---------------------------------------------------------------------------
__device__ __forceinline__ uint32_t s2u(const void* p){
  uint32_t a;
  asm("{ .reg .u64 t; cvta.to.shared.u64 t, %1; cvt.u32.u64 %0, t; }" : "=r"(a) : "l"(p));
  return a;
}
__device__ __forceinline__ void ldsm4(uint32_t* r, uint32_t addr){
  asm volatile("ldmatrix.sync.aligned.m8n8.x4.shared.b16 {%0,%1,%2,%3}, [%4];"
    : "=r"(r[0]), "=r"(r[1]), "=r"(r[2]), "=r"(r[3]) : "r"(addr));
}
__device__ __forceinline__ void bmma(float* c, const uint32_t* a, const uint32_t* b){
  asm volatile("mma.sync.aligned.m16n8k16.row.col.f32.bf16.bf16.f32 "
    "{%0,%1,%2,%3}, {%4,%5,%6,%7}, {%8,%9}, {%0,%1,%2,%3};"
    : "+f"(c[0]), "+f"(c[1]), "+f"(c[2]), "+f"(c[3])
    : "r"(a[0]), "r"(a[1]), "r"(a[2]), "r"(a[3]), "r"(b[0]), "r"(b[1]));
}
__device__ __forceinline__ void hmma(float* c, const uint32_t* a, const uint32_t* b){
  asm volatile("mma.sync.aligned.m16n8k16.row.col.f32.f16.f16.f32 "
    "{%0,%1,%2,%3}, {%4,%5,%6,%7}, {%8,%9}, {%0,%1,%2,%3};"
    : "+f"(c[0]), "+f"(c[1]), "+f"(c[2]), "+f"(c[3])
    : "r"(a[0]), "r"(a[1]), "r"(a[2]), "r"(a[3]), "r"(b[0]), "r"(b[1]));
}
__device__ __forceinline__ void cp16(uint32_t d, const void* s){
  asm volatile("cp.async.cg.shared.global [%0], [%1], 16;" :: "r"(d), "l"(s));
}
__device__ __forceinline__ void cp_commit(){
  asm volatile("cp.async.commit_group;" ::: "memory");
}
template<int N> __device__ __forceinline__ void cp_wait(){
  asm volatile("cp.async.wait_group %0;" :: "n"(N) : "memory");
}

// ===========================================================================
// bf16 split (3-MMA) GEMM, 256 threads: C[128x128] = A * B^T (hi/lo inputs)
// BK=32, 2 stages, smem pitch 80 B.  (proven)
// ===========================================================================
#define BT_TILE  10240
#define BT_STAGE (4*BT_TILE)

template<class EPI>
__device__ __forceinline__ void bgemm_split(
    const __nv_bfloat16* __restrict__ Ah, const __nv_bfloat16* __restrict__ Al, int lda,
    const __nv_bfloat16* __restrict__ Bh, const __nv_bfloat16* __restrict__ Bl, int ldb,
    int m0, int n0, int k1, EPI&& epi)
{
  extern __shared__ __align__(16) char sd[];
  const int t = threadIdx.x, l = t & 31, w = t >> 5;
  const int wm = w & 3, wn = w >> 2;
  const int row = t >> 1, seg = (t & 1) * 16;
  const uint32_t sb = s2u(sd);
  const uint32_t soff = (uint32_t)row*80 + (t & 1)*32;

  const __nv_bfloat16* pAh = Ah + (size_t)(m0 + row)*lda + seg;
  const __nv_bfloat16* pAl = Al + (size_t)(m0 + row)*lda + seg;
  const __nv_bfloat16* pBh = Bh + (size_t)(n0 + row)*ldb + seg;
  const __nv_bfloat16* pBl = Bl + (size_t)(n0 + row)*ldb + seg;

  const int nch = k1 >> 5;
  auto load_stage = [&](int c){
    const int kb = c << 5;
    const uint32_t st = sb + (c & 1)*BT_STAGE + soff;
    cp16(st,               pAh + kb); cp16(st + 16,             pAh + kb + 8);
    cp16(st +   BT_TILE,   pAl + kb); cp16(st +   BT_TILE + 16, pAl + kb + 8);
    cp16(st + 2*BT_TILE,   pBh + kb); cp16(st + 2*BT_TILE + 16, pBh + kb + 8);
    cp16(st + 3*BT_TILE,   pBl + kb); cp16(st + 3*BT_TILE + 16, pBl + kb + 8);
  };
  load_stage(0);
  cp_commit();

  const uint32_t aoff = (uint32_t)(wm*32 + (l & 15))*80 + ((l >> 4) & 1)*16;
  const uint32_t boff = (uint32_t)(wn*64 + (l & 7) + ((l >> 4) & 1)*8)*80
                      + ((l >> 3) & 1)*16;

  float acc[2][8][4] = {};

  for (int c = 0; c < nch; c++){
    cp_wait<0>();
    __syncthreads();
    if (c + 1 < nch) load_stage(c + 1);
    cp_commit();

    const uint32_t base = sb + (c & 1)*BT_STAGE;
    const uint32_t uAh = base + aoff,             uAl = uAh + BT_TILE;
    const uint32_t uBh = base + 2*BT_TILE + boff, uBl = uBh + BT_TILE;

    #pragma unroll
    for (int kf = 0; kf < 2; kf++){
      const uint32_t ko = kf*32;
      uint32_t ah[2][4], al[2][4];
      ldsm4(ah[0], uAh + ko);  ldsm4(ah[1], uAh + ko + 16*80);
      ldsm4(al[0], uAl + ko);  ldsm4(al[1], uAl + ko + 16*80);
      #pragma unroll
      for (int nf2 = 0; nf2 < 4; nf2++){
        uint32_t bh[4], bl[4];
        ldsm4(bh, uBh + ko + nf2*16*80);
        ldsm4(bl, uBl + ko + nf2*16*80);
        #pragma unroll
        for (int mf = 0; mf < 2; mf++){
          bmma(acc[mf][2*nf2],     ah[mf], bh);
          bmma(acc[mf][2*nf2 + 1], ah[mf], bh + 2);
          bmma(acc[mf][2*nf2],     ah[mf], bl);
          bmma(acc[mf][2*nf2 + 1], ah[mf], bl + 2);
          bmma(acc[mf][2*nf2],     al[mf], bh);
          bmma(acc[mf][2*nf2 + 1], al[mf], bh + 2);
        }
      }
    }
  }
  epi(acc);
}

// ===========================================================================
// fp16 single GEMM, 256 threads: C[32 x 256] = A * B^T. BK=32, 2 stages.
// 8 warps on N; warp tile 32(M) x 32(N). For out = P @ K.
// ===========================================================================
#define HA_T 2560                   // A: 32 rows * 80 B
#define HB_T 20480                  // B: 256 rows * 80 B
#define HST  (HA_T + HB_T)          // 23040; 2 stages = 46080

template<class EPI>
__device__ __forceinline__ void hgemm32(
    const __half* __restrict__ A, int lda,
    const __half* __restrict__ B, int ldb,
    int m0, int n0, int k1, EPI&& epi)
{
  extern __shared__ __align__(16) char sd[];
  const int t = threadIdx.x, l = t & 31, w = t >> 5;   // w = wn (0..7)
  const uint32_t sb = s2u(sd);

  // A staging: 32 rows x 4 segs = 128 cp16 (threads t<128)
  const int ar = t >> 2, as = (t & 3) * 8;
  const uint32_t soA = (uint32_t)(t >> 2)*80 + (t & 3)*16;        // t<128: rows 0..31
  const __half* pA = A + (size_t)(m0 + (t >> 2))*lda + as;
  // B staging: 256 rows in 4 groups of 64 (all threads, 4 each)
  const uint32_t soB = (uint32_t)ar*80 + (t & 3)*16;
  const __half* pB = B + (size_t)(n0 + ar)*ldb + as;

  // all warps must be done reading the previous pipeline's buffers
  __syncthreads();

  const int nch = k1 >> 5;
  auto load_stage = [&](int c){
    const int kb = c << 5;
    const uint32_t st = sb + (c & 1)*HST;
    if (t < 128) cp16(st + soA, pA + kb);
    #pragma unroll
    for (int j = 0; j < 4; j++)
      cp16(st + HA_T + soB + (uint32_t)j*64*80, pB + (size_t)j*64*ldb + kb);
  };
  load_stage(0);
  cp_commit();

  const uint32_t aoff = (uint32_t)(l & 15)*80 + ((l >> 4) & 1)*16;
  const uint32_t boff = (uint32_t)(w*32 + (l & 7) + ((l >> 4) & 1)*8)*80
                      + ((l >> 3) & 1)*16;

  float acc[2][4][4] = {};

  for (int c = 0; c < nch; c++){
    cp_wait<0>();
    __syncthreads();
    if (c + 1 < nch) load_stage(c + 1);
    cp_commit();

    const uint32_t base = sb + (c & 1)*HST;
    const uint32_t uA = base + aoff;
    const uint32_t uB = base + HA_T + boff;

    #pragma unroll
    for (int kf = 0; kf < 2; kf++){
      const uint32_t ko = kf*32;
      uint32_t a[2][4];
      ldsm4(a[0], uA + ko);
      ldsm4(a[1], uA + ko + 16*80);
      #pragma unroll
      for (int nf2 = 0; nf2 < 2; nf2++){
        uint32_t b[4];
        ldsm4(b, uB + ko + nf2*16*80);
        #pragma unroll
        for (int mf = 0; mf < 2; mf++){
          hmma(acc[mf][2*nf2],     a[mf], b);
          hmma(acc[mf][2*nf2 + 1], a[mf], b + 2);
        }
      }
    }
  }
  epi(acc);
}

// plain store epilogue (128x128 bf16 gemm)
__device__ __forceinline__ void epi_store(float (&acc)[2][8][4],
                                          float* __restrict__ C, int ldc,
                                          int m0, int n0)
{
  const int t = threadIdx.x, l = t & 31, w = t >> 5;
  const int wm = w & 3, wn = w >> 2;
  #pragma unroll
  for (int mf = 0; mf < 2; mf++){
    const int r0 = m0 + wm*32 + mf*16 + (l >> 2);
    #pragma unroll
    for (int nf = 0; nf < 8; nf++){
      const int cc = n0 + wn*64 + nf*8 + 2*(l & 3);
      *(float2*)&C[(size_t)r0*ldc + cc]     = make_float2(acc[mf][nf][0], acc[mf][nf][1]);
      *(float2*)&C[(size_t)(r0+8)*ldc + cc] = make_float2(acc[mf][nf][2], acc[mf][nf][3]);
    }
  }
}

// ---------------------------------------------------------------------------
// Kernels
// ---------------------------------------------------------------------------
__global__ void __launch_bounds__(256)
k_prep(const float* __restrict__ x, const float* __restrict__ W)
{
  const size_t nx = (size_t)NB*NCTX*DM/4, nw = (size_t)DM*DM/4;
  for (size_t i = blockIdx.x*256 + threadIdx.x; i < nx + nw; i += (size_t)gridDim.x*256){
    float4 v;
    __nv_bfloat16* hi; __nv_bfloat16* lo; size_t j;
    if (i < nx){ v = ((const float4*)x)[i];      hi = g_xhi; lo = g_xlo; j = i; }
    else       { v = ((const float4*)W)[i - nx]; hi = g_Whi; lo = g_Wlo; j = i - nx; }
    __nv_bfloat16 hx = __float2bfloat16_rn(v.x), hy = __float2bfloat16_rn(v.y);
    __nv_bfloat16 hz = __float2bfloat16_rn(v.z), hw = __float2bfloat16_rn(v.w);
    __nv_bfloat162 h01; h01.x = hx; h01.y = hy;
    __nv_bfloat162 h23; h23.x = hz; h23.y = hw;
    __nv_bfloat162 l01; l01.x = __float2bfloat16_rn(v.x - __bfloat162float(hx));
                        l01.y = __float2bfloat16_rn(v.y - __bfloat162float(hy));
    __nv_bfloat162 l23; l23.x = __float2bfloat16_rn(v.z - __bfloat162float(hz));
                        l23.y = __float2bfloat16_rn(v.w - __bfloat162float(hw));
    ((__nv_bfloat162*)hi)[2*j]     = h01;
    ((__nv_bfloat162*)hi)[2*j + 1] = h23;
    ((__nv_bfloat162*)lo)[2*j]     = l01;
    ((__nv_bfloat162*)lo)[2*j + 1] = l23;
  }
}

__global__ void __launch_bounds__(256, 2)
k_proj()
{ // K = x @ W^T -> Khi/Klo (bf16, K-major) and g_Ktb (fp16, transposed)
  const int n0 = blockIdx.x*128, m0 = blockIdx.y*128;
  bgemm_split(g_xhi, g_xlo, DM, g_Whi, g_Wlo, DM, m0, n0, DM,
    [&](float (&acc)[2][8][4]){
      const int t = threadIdx.x, l = t & 31, w = t >> 5;
      const int wm = w & 3, wn = w >> 2;
      #pragma unroll
      for (int mf = 0; mf < 2; mf++){
        const int r0 = m0 + wm*32 + mf*16 + (l >> 2);
        #pragma unroll
        for (int nf = 0; nf < 8; nf++){
          const int cc = n0 + wn*64 + nf*8 + 2*(l & 3);
          #pragma unroll
          for (int hh = 0; hh < 2; hh++){
            const int r = r0 + hh*8;
            const float v0 = acc[mf][nf][2*hh], v1 = acc[mf][nf][2*hh+1];
            __nv_bfloat16 h0 = __float2bfloat16_rn(v0), h1 = __float2bfloat16_rn(v1);
            __nv_bfloat162 hp; hp.x = h0; hp.y = h1;
            __nv_bfloat162 lp;
            lp.x = __float2bfloat16_rn(v0 - __bfloat162float(h0));
            lp.y = __float2bfloat16_rn(v1 - __bfloat162float(h1));
            const size_t ki = (size_t)r*DM + cc;
            *(__nv_bfloat162*)&g_Khi[ki] = hp;
            *(__nv_bfloat162*)&g_Klo[ki] = lp;
            g_Ktb[(size_t)cc    *LDKT + r] = __float2half_rn(v0);
            g_Ktb[(size_t)(cc+1)*LDKT + r] = __float2half_rn(v1);
          }
        }
      }
    });
}

__global__ void __launch_bounds__(256, 2)
k_scores()
{
  const int b  = blockIdx.z;
  const int n0 = blockIdx.x*128, m0 = blockIdx.y*128;
  if (n0 > m0) return;
  const size_t off = (size_t)b*NCTX*DM;
  float* Sb = g_S + (size_t)b*NCTX*NCTX;
  bgemm_split(g_xhi + off, g_xlo + off, DM, g_Khi + off, g_Klo + off, DM,
    m0, n0, DM,
    [&](float (&acc)[2][8][4]){ epi_store(acc, Sb, NCTX, m0, n0); });
}

// ---------------------------------------------------------------------------
// softmax: single global read. Row held in registers (<=16 floats/thread).
// Writes fp16 exp(s-m); g_inv = 1/rowsum; zero-fills P to 128 boundary.
// ---------------------------------------------------------------------------
__device__ __forceinline__ float blk_red(float v, bool is_max)
{
  __shared__ float sm[8];
  const int lane = threadIdx.x & 31, w = threadIdx.x >> 5;
  #pragma unroll
  for (int o = 16; o; o >>= 1){
    float u = __shfl_xor_sync(0xffffffffu, v, o);
    v = is_max ? fmaxf(v, u) : v + u;
  }
  if (lane == 0) sm[w] = v;
  __syncthreads();
  float r = sm[0];
  #pragma unroll
  for (int i = 1; i < 8; i++) r = is_max ? fmaxf(r, sm[i]) : r + sm[i];
  __syncthreads();
  return r;
}

__global__ void __launch_bounds__(256)
k_softmax()
{
  const int row = blockIdx.x;
  const int q   = row & (NCTX - 1);
  const float* p = g_S + (size_t)row * NCTX;
  __half* pb = g_Pb + (size_t)row * NCTX;
  const int len  = q + 1;
  const int len4 = len >> 2;
  const float4* p4 = (const float4*)p;
  __half2* pb2 = (__half2*)pb;

  float4 v[4];
  float tl = 0.f;
  const int tbase = len4 << 2;
  const int tidx  = tbase + threadIdx.x;      // scalar tail element (if any)
  const bool has_tail = (tidx < len);

  float m = -1e30f;
  #pragma unroll
  for (int k = 0; k < 4; k++){
    const int idx = threadIdx.x + (k << 8);
    if (idx < len4){
      v[k] = p4[idx];
      m = fmaxf(m, fmaxf(fmaxf(v[k].x, v[k].y), fmaxf(v[k].z, v[k].w)));
    }
  }
  if (has_tail){ tl = p[tidx]; m = fmaxf(m, tl); }
  m = blk_red(m, true);

  float s = 0.f;
  #pragma unroll
  for (int k = 0; k < 4; k++){
    const int idx = threadIdx.x + (k << 8);
    if (idx < len4){
      float ex = __expf(v[k].x - m), ey = __expf(v[k].y - m);
      float ez = __expf(v[k].z - m), ew = __expf(v[k].w - m);
      s += (ex + ey) + (ez + ew);
      pb2[2*idx]     = __floats2half2_rn(ex, ey);
      pb2[2*idx + 1] = __floats2half2_rn(ez, ew);
    }
  }
  if (has_tail){
    float e = __expf(tl - m);
    s += e;
    pb[tidx] = __float2half_rn(e);
  }
  s = blk_red(s, false);
  if (threadIdx.x == 0) g_inv[row] = 1.f / s;

  const int lenUp = (len + 127) & ~127;
  for (int i = len + threadIdx.x; i < lenUp; i += 256)
    pb[i] = __float2half_rn(0.f);
}

// ---------------------------------------------------------------------------
// out = x + (P @ K) * inv. fp16 single MMA. M_TILE=32, N_TILE=256.
// 256 equal CTAs: pair (i, 127-i) x 2 n-strips x NB. 129 chunks each.
// P read only twice total. No atomics.
// ---------------------------------------------------------------------------
__global__ void __launch_bounds__(256, 2)
k_out_h(const float* __restrict__ x, float* __restrict__ out)
{
  const int b    = blockIdx.z;
  const int n0   = blockIdx.x*256;      // 2 strips
  const int pair = blockIdx.y;          // 0..63
  const __half* Pb = g_Pb  + (size_t)b*NCTX*NCTX;
  const __half* Bt = g_Ktb + (size_t)b*NCTX;

  #pragma unroll
  for (int s = 0; s < 2; s++){
    const int i  = s ? (127 - pair) : pair;
    const int m0 = i*32;
    hgemm32(Pb, NCTX, Bt, LDKT, m0, n0, (i + 1)*32,
      [&](float (&acc)[2][4][4]){
        const int t = threadIdx.x, l = t & 31, w = t >> 5;
        #pragma unroll
        for (int mf = 0; mf < 2; mf++){
          const int r0 = m0 + mf*16 + (l >> 2);
          const float inv0 = g_inv[b*NCTX + r0];
          const float inv1 = g_inv[b*NCTX + r0 + 8];
          #pragma unroll
          for (int nf = 0; nf < 4; nf++){
            const int cc = n0 + w*32 + nf*8 + 2*(l & 3);
            const size_t i0 = (size_t)b*NCTX*DM + (size_t)r0*DM + cc;
            const size_t i1 = i0 + (size_t)8*DM;
            *(float2*)&out[i0] = make_float2(acc[mf][nf][0]*inv0 + x[i0],
                                             acc[mf][nf][1]*inv0 + x[i0+1]);
            *(float2*)&out[i1] = make_float2(acc[mf][nf][2]*inv1 + x[i1],
                                             acc[mf][nf][3]*inv1 + x[i1+1]);
          }
        }
      });
  }
}

// ---------------------------------------------------------------------------
extern "C" void kernel_launch(void* const* d_in, const int* in_sizes, int n_in,
                              void* d_out, int out_size)
{
  const float* x = (const float*)d_in[0];
  const float* W = (const float*)d_in[1];
  float* out = (float*)d_out;

  const int SMEM_BF  = 2 * BT_STAGE;     // 81920
  const int SMEM_OUT = 2 * HST;          // 46080
  cudaFuncSetAttribute(k_proj,   cudaFuncAttributeMaxDynamicSharedMemorySize, SMEM_BF);
  cudaFuncSetAttribute(k_scores, cudaFuncAttributeMaxDynamicSharedMemorySize, SMEM_BF);
  cudaFuncSetAttribute(k_out_h,  cudaFuncAttributeMaxDynamicSharedMemorySize, SMEM_OUT);

  k_prep   <<<1184, 256>>>(x, W);
  k_proj   <<<dim3(4, 64),      256, SMEM_BF>>>();
  k_scores <<<dim3(32, 32, NB), 256, SMEM_BF>>>();
  k_softmax<<<NB * NCTX, 256>>>();
  k_out_h  <<<dim3(2, 64, NB),  256, SMEM_OUT>>>(x, out);
}

// round 14
// speedup vs baseline: 1.0619x; 1.0619x over previous
#include <cuda_runtime.h>
#include <cuda_bf16.h>
#include <cuda_fp16.h>
#include <cstdint>

#define NCTX 4096
#define DM   512
#define NB   2
#define LDKT (NB*NCTX)

// Scratch
__device__ __nv_bfloat16 g_xhi[(size_t)NB*NCTX*DM];
__device__ __nv_bfloat16 g_xlo[(size_t)NB*NCTX*DM];
__device__ __nv_bfloat16 g_Whi[(size_t)DM*DM];
__device__ __nv_bfloat16 g_Wlo[(size_t)DM*DM];
__device__ __nv_bfloat16 g_Khi[(size_t)NB*NCTX*DM];
__device__ __nv_bfloat16 g_Klo[(size_t)NB*NCTX*DM];
__device__ __half        g_Ktb[(size_t)DM*NB*NCTX];   // fp16 K^T
__device__ float         g_S  [(size_t)NB*NCTX*NCTX]; // fp32 scores
__device__ __half        g_Pb [(size_t)NB*NCTX*NCTX]; // fp16 exp(s-m)
__device__ float         g_inv[(size_t)NB*NCTX];      // 1 / rowsum(exp)

// ---------------------------------------------------------------------------
// helpers
// ---------------------------------------------------------------------------
__device__ __forceinline__ uint32_t s2u(const void* p){
  uint32_t a;
  asm("{ .reg .u64 t; cvta.to.shared.u64 t, %1; cvt.u32.u64 %0, t; }" : "=r"(a) : "l"(p));
  return a;
}
__device__ __forceinline__ void ldsm4(uint32_t* r, uint32_t addr){
  asm volatile("ldmatrix.sync.aligned.m8n8.x4.shared.b16 {%0,%1,%2,%3}, [%4];"
    : "=r"(r[0]), "=r"(r[1]), "=r"(r[2]), "=r"(r[3]) : "r"(addr));
}
__device__ __forceinline__ void bmma(float* c, const uint32_t* a, const uint32_t* b){
  asm volatile("mma.sync.aligned.m16n8k16.row.col.f32.bf16.bf16.f32 "
    "{%0,%1,%2,%3}, {%4,%5,%6,%7}, {%8,%9}, {%0,%1,%2,%3};"
    : "+f"(c[0]), "+f"(c[1]), "+f"(c[2]), "+f"(c[3])
    : "r"(a[0]), "r"(a[1]), "r"(a[2]), "r"(a[3]), "r"(b[0]), "r"(b[1]));
}
__device__ __forceinline__ void hmma(float* c, const uint32_t* a, const uint32_t* b){
  asm volatile("mma.sync.aligned.m16n8k16.row.col.f32.f16.f16.f32 "
    "{%0,%1,%2,%3}, {%4,%5,%6,%7}, {%8,%9}, {%0,%1,%2,%3};"
    : "+f"(c[0]), "+f"(c[1]), "+f"(c[2]), "+f"(c[3])
    : "r"(a[0]), "r"(a[1]), "r"(a[2]), "r"(a[3]), "r"(b[0]), "r"(b[1]));
}
__device__ __forceinline__ void cp16(uint32_t d, const void* s){
  asm volatile("cp.async.cg.shared.global [%0], [%1], 16;" :: "r"(d), "l"(s));
}
__device__ __forceinline__ void cp_commit(){
  asm volatile("cp.async.commit_group;" ::: "memory");
}
template<int N> __device__ __forceinline__ void cp_wait(){
  asm volatile("cp.async.wait_group %0;" :: "n"(N) : "memory");
}

// ===========================================================================
// bf16 split (3-MMA) GEMM, 256 threads: C[128x128] = A * B^T (hi/lo inputs)
// BK=32, 2 stages, smem pitch 80 B.  (proven)
// ===========================================================================
#define BT_TILE  10240
#define BT_STAGE (4*BT_TILE)

template<class EPI>
__device__ __forceinline__ void bgemm_split(
    const __nv_bfloat16* __restrict__ Ah, const __nv_bfloat16* __restrict__ Al, int lda,
    const __nv_bfloat16* __restrict__ Bh, const __nv_bfloat16* __restrict__ Bl, int ldb,
    int m0, int n0, int k1, EPI&& epi)
{
  extern __shared__ __align__(16) char sd[];
  const int t = threadIdx.x, l = t & 31, w = t >> 5;
  const int wm = w & 3, wn = w >> 2;
  const int row = t >> 1, seg = (t & 1) * 16;
  const uint32_t sb = s2u(sd);
  const uint32_t soff = (uint32_t)row*80 + (t & 1)*32;

  const __nv_bfloat16* pAh = Ah + (size_t)(m0 + row)*lda + seg;
  const __nv_bfloat16* pAl = Al + (size_t)(m0 + row)*lda + seg;
  const __nv_bfloat16* pBh = Bh + (size_t)(n0 + row)*ldb + seg;
  const __nv_bfloat16* pBl = Bl + (size_t)(n0 + row)*ldb + seg;

  const int nch = k1 >> 5;
  auto load_stage = [&](int c){
    const int kb = c << 5;
    const uint32_t st = sb + (c & 1)*BT_STAGE + soff;
    cp16(st,               pAh + kb); cp16(st + 16,             pAh + kb + 8);
    cp16(st +   BT_TILE,   pAl + kb); cp16(st +   BT_TILE + 16, pAl + kb + 8);
    cp16(st + 2*BT_TILE,   pBh + kb); cp16(st + 2*BT_TILE + 16, pBh + kb + 8);
    cp16(st + 3*BT_TILE,   pBl + kb); cp16(st + 3*BT_TILE + 16, pBl + kb + 8);
  };
  load_stage(0);
  cp_commit();

  const uint32_t aoff = (uint32_t)(wm*32 + (l & 15))*80 + ((l >> 4) & 1)*16;
  const uint32_t boff = (uint32_t)(wn*64 + (l & 7) + ((l >> 4) & 1)*8)*80
                      + ((l >> 3) & 1)*16;

  float acc[2][8][4] = {};

  for (int c = 0; c < nch; c++){
    cp_wait<0>();
    __syncthreads();
    if (c + 1 < nch) load_stage(c + 1);
    cp_commit();

    const uint32_t base = sb + (c & 1)*BT_STAGE;
    const uint32_t uAh = base + aoff,             uAl = uAh + BT_TILE;
    const uint32_t uBh = base + 2*BT_TILE + boff, uBl = uBh + BT_TILE;

    #pragma unroll
    for (int kf = 0; kf < 2; kf++){
      const uint32_t ko = kf*32;
      uint32_t ah[2][4], al[2][4];
      ldsm4(ah[0], uAh + ko);  ldsm4(ah[1], uAh + ko + 16*80);
      ldsm4(al[0], uAl + ko);  ldsm4(al[1], uAl + ko + 16*80);
      #pragma unroll
      for (int nf2 = 0; nf2 < 4; nf2++){
        uint32_t bh[4], bl[4];
        ldsm4(bh, uBh + ko + nf2*16*80);
        ldsm4(bl, uBl + ko + nf2*16*80);
        #pragma unroll
        for (int mf = 0; mf < 2; mf++){
          bmma(acc[mf][2*nf2],     ah[mf], bh);
          bmma(acc[mf][2*nf2 + 1], ah[mf], bh + 2);
          bmma(acc[mf][2*nf2],     ah[mf], bl);
          bmma(acc[mf][2*nf2 + 1], ah[mf], bl + 2);
          bmma(acc[mf][2*nf2],     al[mf], bh);
          bmma(acc[mf][2*nf2 + 1], al[mf], bh + 2);
        }
      }
    }
  }
  epi(acc);
}

// ===========================================================================
// fp16 single GEMM, 256 threads: C[64 x 128] = A * B^T. BK=32, 2 stages.
// 8 warps = 2(M) x 4(N); warp tile 32 x 32. For out = P @ K.  (R12 proven)
// ===========================================================================
#define KA_T 5120                   // A: 64 rows * 80 B
#define KB_T 10240                  // B: 128 rows * 80 B
#define KST  (KA_T + KB_T)          // 15360; 2 stages = 30720

template<class EPI>
__device__ __forceinline__ void hgemm_out(
    const __half* __restrict__ A, int lda,
    const __half* __restrict__ B, int ldb,
    int m0, int n0, int k1, EPI&& epi)
{
  extern __shared__ __align__(16) char sd[];
  const int t = threadIdx.x, l = t & 31, w = t >> 5;
  const int wm = w & 1, wn = w >> 1;
  const uint32_t sb = s2u(sd);

  const int ar = t >> 2, as = (t & 3) * 8;     // row 0..63, 16B seg
  const uint32_t soA = (uint32_t)ar*80 + (t & 3)*16;
  const __half* pA = A + (size_t)(m0 + ar)*lda + as;
  const __half* pB = B + (size_t)(n0 + ar)*ldb + as;   // rows ar, ar+64

  const int nch = k1 >> 5;
  auto load_stage = [&](int c){
    const int kb = c << 5;
    const uint32_t st = sb + (c & 1)*KST;
    cp16(st + soA, pA + kb);
    cp16(st + KA_T + soA,        pB + kb);
    cp16(st + KA_T + soA + KA_T, pB + (size_t)64*ldb + kb);
  };
  load_stage(0);
  cp_commit();

  const uint32_t aoff = (uint32_t)(wm*32 + (l & 15))*80 + ((l >> 4) & 1)*16;
  const uint32_t boff = (uint32_t)(wn*32 + (l & 7) + ((l >> 4) & 1)*8)*80
                      + ((l >> 3) & 1)*16;

  float acc[2][4][4] = {};

  for (int c = 0; c < nch; c++){
    cp_wait<0>();
    __syncthreads();
    if (c + 1 < nch) load_stage(c + 1);
    cp_commit();

    const uint32_t base = sb + (c & 1)*KST;
    const uint32_t uA = base + aoff;
    const uint32_t uB = base + KA_T + boff;

    #pragma unroll
    for (int kf = 0; kf < 2; kf++){
      const uint32_t ko = kf*32;
      uint32_t a[2][4];
      ldsm4(a[0], uA + ko);
      ldsm4(a[1], uA + ko + 16*80);
      #pragma unroll
      for (int nf2 = 0; nf2 < 2; nf2++){
        uint32_t b[4];
        ldsm4(b, uB + ko + nf2*16*80);
        #pragma unroll
        for (int mf = 0; mf < 2; mf++){
          hmma(acc[mf][2*nf2],     a[mf], b);
          hmma(acc[mf][2*nf2 + 1], a[mf], b + 2);
        }
      }
    }
  }
  epi(acc);
}

// plain store epilogue (128x128 bf16 gemm)
__device__ __forceinline__ void epi_store(float (&acc)[2][8][4],
                                          float* __restrict__ C, int ldc,
                                          int m0, int n0)
{
  const int t = threadIdx.x, l = t & 31, w = t >> 5;
  const int wm = w & 3, wn = w >> 2;
  #pragma unroll
  for (int mf = 0; mf < 2; mf++){
    const int r0 = m0 + wm*32 + mf*16 + (l >> 2);
    #pragma unroll
    for (int nf = 0; nf < 8; nf++){
      const int cc = n0 + wn*64 + nf*8 + 2*(l & 3);
      *(float2*)&C[(size_t)r0*ldc + cc]     = make_float2(acc[mf][nf][0], acc[mf][nf][1]);
      *(float2*)&C[(size_t)(r0+8)*ldc + cc] = make_float2(acc[mf][nf][2], acc[mf][nf][3]);
    }
  }
}

// ---------------------------------------------------------------------------
// Kernels
// ---------------------------------------------------------------------------
__global__ void __launch_bounds__(256)
k_prep(const float* __restrict__ x, const float* __restrict__ W)
{
  const size_t nx = (size_t)NB*NCTX*DM/4, nw = (size_t)DM*DM/4;
  for (size_t i = blockIdx.x*256 + threadIdx.x; i < nx + nw; i += (size_t)gridDim.x*256){
    float4 v;
    __nv_bfloat16* hi; __nv_bfloat16* lo; size_t j;
    if (i < nx){ v = ((const float4*)x)[i];      hi = g_xhi; lo = g_xlo; j = i; }
    else       { v = ((const float4*)W)[i - nx]; hi = g_Whi; lo = g_Wlo; j = i - nx; }
    __nv_bfloat16 hx = __float2bfloat16_rn(v.x), hy = __float2bfloat16_rn(v.y);
    __nv_bfloat16 hz = __float2bfloat16_rn(v.z), hw = __float2bfloat16_rn(v.w);
    __nv_bfloat162 h01; h01.x = hx; h01.y = hy;
    __nv_bfloat162 h23; h23.x = hz; h23.y = hw;
    __nv_bfloat162 l01; l01.x = __float2bfloat16_rn(v.x - __bfloat162float(hx));
                        l01.y = __float2bfloat16_rn(v.y - __bfloat162float(hy));
    __nv_bfloat162 l23; l23.x = __float2bfloat16_rn(v.z - __bfloat162float(hz));
                        l23.y = __float2bfloat16_rn(v.w - __bfloat162float(hw));
    ((__nv_bfloat162*)hi)[2*j]     = h01;
    ((__nv_bfloat162*)hi)[2*j + 1] = h23;
    ((__nv_bfloat162*)lo)[2*j]     = l01;
    ((__nv_bfloat162*)lo)[2*j + 1] = l23;
  }
}

__global__ void __launch_bounds__(256, 2)
k_proj()
{ // K = x @ W^T -> Khi/Klo (bf16, K-major) and g_Ktb (fp16, transposed)
  const int n0 = blockIdx.x*128, m0 = blockIdx.y*128;
  bgemm_split(g_xhi, g_xlo, DM, g_Whi, g_Wlo, DM, m0, n0, DM,
    [&](float (&acc)[2][8][4]){
      const int t = threadIdx.x, l = t & 31, w = t >> 5;
      const int wm = w & 3, wn = w >> 2;
      #pragma unroll
      for (int mf = 0; mf < 2; mf++){
        const int r0 = m0 + wm*32 + mf*16 + (l >> 2);
        #pragma unroll
        for (int nf = 0; nf < 8; nf++){
          const int cc = n0 + wn*64 + nf*8 + 2*(l & 3);
          #pragma unroll
          for (int hh = 0; hh < 2; hh++){
            const int r = r0 + hh*8;
            const float v0 = acc[mf][nf][2*hh], v1 = acc[mf][nf][2*hh+1];
            __nv_bfloat16 h0 = __float2bfloat16_rn(v0), h1 = __float2bfloat16_rn(v1);
            __nv_bfloat162 hp; hp.x = h0; hp.y = h1;
            __nv_bfloat162 lp;
            lp.x = __float2bfloat16_rn(v0 - __bfloat162float(h0));
            lp.y = __float2bfloat16_rn(v1 - __bfloat162float(h1));
            const size_t ki = (size_t)r*DM + cc;
            *(__nv_bfloat162*)&g_Khi[ki] = hp;
            *(__nv_bfloat162*)&g_Klo[ki] = lp;
            g_Ktb[(size_t)cc    *LDKT + r] = __float2half_rn(v0);
            g_Ktb[(size_t)(cc+1)*LDKT + r] = __float2half_rn(v1);
          }
        }
      }
    });
}

__global__ void __launch_bounds__(256, 2)
k_scores()
{
  const int b  = blockIdx.z;
  const int n0 = blockIdx.x*128, m0 = blockIdx.y*128;
  if (n0 > m0) return;
  const size_t off = (size_t)b*NCTX*DM;
  float* Sb = g_S + (size_t)b*NCTX*NCTX;
  bgemm_split(g_xhi + off, g_xlo + off, DM, g_Khi + off, g_Klo + off, DM,
    m0, n0, DM,
    [&](float (&acc)[2][8][4]){ epi_store(acc, Sb, NCTX, m0, n0); });
}

// ---------------------------------------------------------------------------
// softmax: single global read; row held in registers (<=16 floats/thread).
// Writes fp16 exp(s-m); g_inv = 1/rowsum; zero-fills P to 128 boundary.
// ---------------------------------------------------------------------------
__device__ __forceinline__ float blk_red(float v, bool is_max)
{
  __shared__ float sm[8];
  const int lane = threadIdx.x & 31, w = threadIdx.x >> 5;
  #pragma unroll
  for (int o = 16; o; o >>= 1){
    float u = __shfl_xor_sync(0xffffffffu, v, o);
    v = is_max ? fmaxf(v, u) : v + u;
  }
  if (lane == 0) sm[w] = v;
  __syncthreads();
  float r = sm[0];
  #pragma unroll
  for (int i = 1; i < 8; i++) r = is_max ? fmaxf(r, sm[i]) : r + sm[i];
  __syncthreads();
  return r;
}

__global__ void __launch_bounds__(256)
k_softmax()
{
  const int row = blockIdx.x;
  const int q   = row & (NCTX - 1);
  const float* p = g_S + (size_t)row * NCTX;
  __half* pb = g_Pb + (size_t)row * NCTX;
  const int len  = q + 1;
  const int len4 = len >> 2;
  const float4* p4 = (const float4*)p;
  __half2* pb2 = (__half2*)pb;

  float4 v[4];
  float tl = 0.f;
  const int tbase = len4 << 2;
  const int tidx  = tbase + threadIdx.x;
  const bool has_tail = (tidx < len);

  float m = -1e30f;
  #pragma unroll
  for (int k = 0; k < 4; k++){
    const int idx = threadIdx.x + (k << 8);
    if (idx < len4){
      v[k] = p4[idx];
      m = fmaxf(m, fmaxf(fmaxf(v[k].x, v[k].y), fmaxf(v[k].z, v[k].w)));
    }
  }
  if (has_tail){ tl = p[tidx]; m = fmaxf(m, tl); }
  m = blk_red(m, true);

  float s = 0.f;
  #pragma unroll
  for (int k = 0; k < 4; k++){
    const int idx = threadIdx.x + (k << 8);
    if (idx < len4){
      float ex = __expf(v[k].x - m), ey = __expf(v[k].y - m);
      float ez = __expf(v[k].z - m), ew = __expf(v[k].w - m);
      s += (ex + ey) + (ez + ew);
      pb2[2*idx]     = __floats2half2_rn(ex, ey);
      pb2[2*idx + 1] = __floats2half2_rn(ez, ew);
    }
  }
  if (has_tail){
    float e = __expf(tl - m);
    s += e;
    pb[tidx] = __float2half_rn(e);
  }
  s = blk_red(s, false);
  if (threadIdx.x == 0) g_inv[row] = 1.f / s;

  const int lenUp = (len + 127) & ~127;
  for (int i = len + threadIdx.x; i < lenUp; i += 256)
    pb[i] = __float2half_rn(0.f);
}

// ---------------------------------------------------------------------------
// out = x + (P @ K) * inv. fp16 single MMA. M_TILE=64, N_TILE=128.
// 256 equal CTAs: pair (i, 63-i) x 4 n-strips. No atomics.  (R12 proven)
// ---------------------------------------------------------------------------
__global__ void __launch_bounds__(256, 2)
k_out_h(const float* __restrict__ x, float* __restrict__ out)
{
  const int b    = blockIdx.z;
  const int n0   = blockIdx.x*128;      // 4 strips
  const int pair = blockIdx.y;          // 0..31
  const __half* Pb = g_Pb  + (size_t)b*NCTX*NCTX;
  const __half* Bt = g_Ktb + (size_t)b*NCTX;

  #pragma unroll
  for (int s = 0; s < 2; s++){
    const int i  = s ? (63 - pair) : pair;
    const int m0 = i*64;
    hgemm_out(Pb, NCTX, Bt, LDKT, m0, n0, (i + 1)*64,
      [&](float (&acc)[2][4][4]){
        const int t = threadIdx.x, l = t & 31, w = t >> 5;
        const int wm = w & 1, wn = w >> 1;
        #pragma unroll
        for (int mf = 0; mf < 2; mf++){
          const int r0 = m0 + wm*32 + mf*16 + (l >> 2);
          const float inv0 = g_inv[b*NCTX + r0];
          const float inv1 = g_inv[b*NCTX + r0 + 8];
          #pragma unroll
          for (int nf = 0; nf < 4; nf++){
            const int cc = n0 + wn*32 + nf*8 + 2*(l & 3);
            const size_t i0 = (size_t)b*NCTX*DM + (size_t)r0*DM + cc;
            const size_t i1 = i0 + (size_t)8*DM;
            *(float2*)&out[i0] = make_float2(acc[mf][nf][0]*inv0 + x[i0],
                                             acc[mf][nf][1]*inv0 + x[i0+1]);
            *(float2*)&out[i1] = make_float2(acc[mf][nf][2]*inv1 + x[i1],
                                             acc[mf][nf][3]*inv1 + x[i1+1]);
          }
        }
      });
  }
}

// ---------------------------------------------------------------------------
extern "C" void kernel_launch(void* const* d_in, const int* in_sizes, int n_in,
                              void* d_out, int out_size)
{
  const float* x = (const float*)d_in[0];
  const float* W = (const float*)d_in[1];
  float* out = (float*)d_out;

  const int SMEM_BF  = 2 * BT_STAGE;     // 81920
  const int SMEM_OUT = 2 * KST;          // 30720
  cudaFuncSetAttribute(k_proj,   cudaFuncAttributeMaxDynamicSharedMemorySize, SMEM_BF);
  cudaFuncSetAttribute(k_scores, cudaFuncAttributeMaxDynamicSharedMemorySize, SMEM_BF);
  cudaFuncSetAttribute(k_out_h,  cudaFuncAttributeMaxDynamicSharedMemorySize, SMEM_OUT);

  k_prep   <<<1184, 256>>>(x, W);
  k_proj   <<<dim3(4, 64),      256, SMEM_BF>>>();
  k_scores <<<dim3(32, 32, NB), 256, SMEM_BF>>>();
  k_softmax<<<NB * NCTX, 256>>>();
  k_out_h  <<<dim3(4, 32, NB),  256, SMEM_OUT>>>(x, out);
}

// round 15
// speedup vs baseline: 1.0991x; 1.0351x over previous
#include <cuda_runtime.h>
#include <cuda_bf16.h>
#include <cuda_fp16.h>
#include <cstdint>

#define NCTX 4096
#define DM   512
#define NB   2
#define LDKT (NB*NCTX)

// Scratch
__device__ __nv_bfloat16 g_xhi[(size_t)NB*NCTX*DM];
__device__ __nv_bfloat16 g_xlo[(size_t)NB*NCTX*DM];
__device__ __nv_bfloat16 g_Whi[(size_t)DM*DM];
__device__ __nv_bfloat16 g_Wlo[(size_t)DM*DM];
__device__ __nv_bfloat16 g_Khi[(size_t)NB*NCTX*DM];
__device__ __nv_bfloat16 g_Klo[(size_t)NB*NCTX*DM];
__device__ __half        g_Ktb[(size_t)DM*NB*NCTX];   // fp16 K^T
__device__ float         g_S  [(size_t)NB*NCTX*NCTX]; // fp32 scores
__device__ __half        g_Pb [(size_t)NB*NCTX*NCTX]; // fp16 exp(s-m)
__device__ float         g_inv[(size_t)NB*NCTX];      // 1 / rowsum(exp)

// ---------------------------------------------------------------------------
// helpers
// ---------------------------------------------------------------------------
__device__ __forceinline__ uint32_t s2u(const void* p){
  uint32_t a;
  asm("{ .reg .u64 t; cvta.to.shared.u64 t, %1; cvt.u32.u64 %0, t; }" : "=r"(a) : "l"(p));
  return a;
}
__device__ __forceinline__ void ldsm4(uint32_t* r, uint32_t addr){
  asm volatile("ldmatrix.sync.aligned.m8n8.x4.shared.b16 {%0,%1,%2,%3}, [%4];"
    : "=r"(r[0]), "=r"(r[1]), "=r"(r[2]), "=r"(r[3]) : "r"(addr));
}
__device__ __forceinline__ void bmma(float* c, const uint32_t* a, const uint32_t* b){
  asm volatile("mma.sync.aligned.m16n8k16.row.col.f32.bf16.bf16.f32 "
    "{%0,%1,%2,%3}, {%4,%5,%6,%7}, {%8,%9}, {%0,%1,%2,%3};"
    : "+f"(c[0]), "+f"(c[1]), "+f"(c[2]), "+f"(c[3])
    : "r"(a[0]), "r"(a[1]), "r"(a[2]), "r"(a[3]), "r"(b[0]), "r"(b[1]));
}
__device__ __forceinline__ void hmma(float* c, const uint32_t* a, const uint32_t* b){
  asm volatile("mma.sync.aligned.m16n8k16.row.col.f32.f16.f16.f32 "
    "{%0,%1,%2,%3}, {%4,%5,%6,%7}, {%8,%9}, {%0,%1,%2,%3};"
    : "+f"(c[0]), "+f"(c[1]), "+f"(c[2]), "+f"(c[3])
    : "r"(a[0]), "r"(a[1]), "r"(a[2]), "r"(a[3]), "r"(b[0]), "r"(b[1]));
}
__device__ __forceinline__ void cp16(uint32_t d, const void* s){
  asm volatile("cp.async.cg.shared.global [%0], [%1], 16;" :: "r"(d), "l"(s));
}
__device__ __forceinline__ void cp_commit(){
  asm volatile("cp.async.commit_group;" ::: "memory");
}
template<int N> __device__ __forceinline__ void cp_wait(){
  asm volatile("cp.async.wait_group %0;" :: "n"(N) : "memory");
}

// ===========================================================================
// bf16 split (3-MMA) GEMM, 256 threads: C[128x128] = A * B^T (hi/lo inputs)
// BK=32, 2 stages, smem pitch 80 B.
// Inner loop term-major ordered: same-accumulator reuse distance = 8 MMAs
// (covers HMMA latency; R14's distance-2 chains stalled the tensor pipe).
// ===========================================================================
#define BT_TILE  10240
#define BT_STAGE (4*BT_TILE)

template<class EPI>
__device__ __forceinline__ void bgemm_split(
    const __nv_bfloat16* __restrict__ Ah, const __nv_bfloat16* __restrict__ Al, int lda,
    const __nv_bfloat16* __restrict__ Bh, const __nv_bfloat16* __restrict__ Bl, int ldb,
    int m0, int n0, int k1, EPI&& epi)
{
  extern __shared__ __align__(16) char sd[];
  const int t = threadIdx.x, l = t & 31, w = t >> 5;
  const int wm = w & 3, wn = w >> 2;
  const int row = t >> 1, seg = (t & 1) * 16;
  const uint32_t sb = s2u(sd);
  const uint32_t soff = (uint32_t)row*80 + (t & 1)*32;

  const __nv_bfloat16* pAh = Ah + (size_t)(m0 + row)*lda + seg;
  const __nv_bfloat16* pAl = Al + (size_t)(m0 + row)*lda + seg;
  const __nv_bfloat16* pBh = Bh + (size_t)(n0 + row)*ldb + seg;
  const __nv_bfloat16* pBl = Bl + (size_t)(n0 + row)*ldb + seg;

  const int nch = k1 >> 5;
  auto load_stage = [&](int c){
    const int kb = c << 5;
    const uint32_t st = sb + (c & 1)*BT_STAGE + soff;
    cp16(st,               pAh + kb); cp16(st + 16,             pAh + kb + 8);
    cp16(st +   BT_TILE,   pAl + kb); cp16(st +   BT_TILE + 16, pAl + kb + 8);
    cp16(st + 2*BT_TILE,   pBh + kb); cp16(st + 2*BT_TILE + 16, pBh + kb + 8);
    cp16(st + 3*BT_TILE,   pBl + kb); cp16(st + 3*BT_TILE + 16, pBl + kb + 8);
  };
  load_stage(0);
  cp_commit();

  const uint32_t aoff = (uint32_t)(wm*32 + (l & 15))*80 + ((l >> 4) & 1)*16;
  const uint32_t boff = (uint32_t)(wn*64 + (l & 7) + ((l >> 4) & 1)*8)*80
                      + ((l >> 3) & 1)*16;

  float acc[2][8][4] = {};

  for (int c = 0; c < nch; c++){
    cp_wait<0>();
    __syncthreads();
    if (c + 1 < nch) load_stage(c + 1);
    cp_commit();

    const uint32_t base = sb + (c & 1)*BT_STAGE;
    const uint32_t uAh = base + aoff,             uAl = uAh + BT_TILE;
    const uint32_t uBh = base + 2*BT_TILE + boff, uBl = uBh + BT_TILE;

    #pragma unroll
    for (int kf = 0; kf < 2; kf++){
      const uint32_t ko = kf*32;
      uint32_t ah[2][4], al[2][4];
      ldsm4(ah[0], uAh + ko);  ldsm4(ah[1], uAh + ko + 16*80);
      ldsm4(al[0], uAl + ko);  ldsm4(al[1], uAl + ko + 16*80);
      #pragma unroll
      for (int h = 0; h < 2; h++){          // nf2 pair {2h, 2h+1}
        uint32_t bh[2][4], bl[2][4];
        ldsm4(bh[0], uBh + ko + (2*h    )*16*80);
        ldsm4(bh[1], uBh + ko + (2*h + 1)*16*80);
        ldsm4(bl[0], uBl + ko + (2*h    )*16*80);
        ldsm4(bl[1], uBl + ko + (2*h + 1)*16*80);
        // term hh: 8 MMAs, 8 distinct accumulators
        #pragma unroll
        for (int j = 0; j < 2; j++)
          #pragma unroll
          for (int mf = 0; mf < 2; mf++){
            bmma(acc[mf][2*(2*h+j)],     ah[mf], bh[j]);
            bmma(acc[mf][2*(2*h+j) + 1], ah[mf], bh[j] + 2);
          }
        // term hl
        #pragma unroll
        for (int j = 0; j < 2; j++)
          #pragma unroll
          for (int mf = 0; mf < 2; mf++){
            bmma(acc[mf][2*(2*h+j)],     ah[mf], bl[j]);
            bmma(acc[mf][2*(2*h+j) + 1], ah[mf], bl[j] + 2);
          }
        // term lh
        #pragma unroll
        for (int j = 0; j < 2; j++)
          #pragma unroll
          for (int mf = 0; mf < 2; mf++){
            bmma(acc[mf][2*(2*h+j)],     al[mf], bh[j]);
            bmma(acc[mf][2*(2*h+j) + 1], al[mf], bh[j] + 2);
          }
      }
    }
  }
  epi(acc);
}

// ===========================================================================
// fp16 single GEMM, 256 threads: C[64 x 128] = A * B^T. BK=32, 3 stages.
// 8 warps = 2(M) x 4(N); warp tile 32 x 32. For out = P @ K.
// ===========================================================================
#define KA_T 5120                   // A: 64 rows * 80 B
#define KB_T 10240                  // B: 128 rows * 80 B
#define KST  (KA_T + KB_T)          // 15360; 3 stages = 46080

template<class EPI>
__device__ __forceinline__ void hgemm_out(
    const __half* __restrict__ A, int lda,
    const __half* __restrict__ B, int ldb,
    int m0, int n0, int k1, EPI&& epi)
{
  extern __shared__ __align__(16) char sd[];
  const int t = threadIdx.x, l = t & 31, w = t >> 5;
  const int wm = w & 1, wn = w >> 1;
  const uint32_t sb = s2u(sd);

  const int ar = t >> 2, as = (t & 3) * 8;     // row 0..63, 16B seg
  const uint32_t soA = (uint32_t)ar*80 + (t & 3)*16;
  const __half* pA = A + (size_t)(m0 + ar)*lda + as;
  const __half* pB = B + (size_t)(n0 + ar)*ldb + as;   // rows ar, ar+64

  // drain previous call's pipeline (buffer reuse across sequential calls)
  cp_wait<0>();
  __syncthreads();

  const int nch = k1 >> 5;
  auto load_stage = [&](int c){
    const int kb = c << 5;
    const uint32_t st = sb + (c % 3)*KST;
    cp16(st + soA, pA + kb);
    cp16(st + KA_T + soA,        pB + kb);
    cp16(st + KA_T + soA + KA_T, pB + (size_t)64*ldb + kb);
  };
  load_stage(0); cp_commit();
  if (1 < nch) load_stage(1);
  cp_commit();

  const uint32_t aoff = (uint32_t)(wm*32 + (l & 15))*80 + ((l >> 4) & 1)*16;
  const uint32_t boff = (uint32_t)(wn*32 + (l & 7) + ((l >> 4) & 1)*8)*80
                      + ((l >> 3) & 1)*16;

  float acc[2][4][4] = {};

  for (int c = 0; c < nch; c++){
    cp_wait<1>();
    __syncthreads();
    if (c + 2 < nch) load_stage(c + 2);
    cp_commit();

    const uint32_t base = sb + (c % 3)*KST;
    const uint32_t uA = base + aoff;
    const uint32_t uB = base + KA_T + boff;

    #pragma unroll
    for (int kf = 0; kf < 2; kf++){
      const uint32_t ko = kf*32;
      uint32_t a[2][4];
      ldsm4(a[0], uA + ko);
      ldsm4(a[1], uA + ko + 16*80);
      #pragma unroll
      for (int nf2 = 0; nf2 < 2; nf2++){
        uint32_t b[4];
        ldsm4(b, uB + ko + nf2*16*80);
        #pragma unroll
        for (int mf = 0; mf < 2; mf++){
          hmma(acc[mf][2*nf2],     a[mf], b);
          hmma(acc[mf][2*nf2 + 1], a[mf], b + 2);
        }
      }
    }
    // keep the next chunk's data arriving while we compute: the sync at the
    // top of the loop orders buffer reuse (3 buffers, distance 2 in flight)
  }
  epi(acc);
}

// plain store epilogue (128x128 bf16 gemm)
__device__ __forceinline__ void epi_store(float (&acc)[2][8][4],
                                          float* __restrict__ C, int ldc,
                                          int m0, int n0)
{
  const int t = threadIdx.x, l = t & 31, w = t >> 5;
  const int wm = w & 3, wn = w >> 2;
  #pragma unroll
  for (int mf = 0; mf < 2; mf++){
    const int r0 = m0 + wm*32 + mf*16 + (l >> 2);
    #pragma unroll
    for (int nf = 0; nf < 8; nf++){
      const int cc = n0 + wn*64 + nf*8 + 2*(l & 3);
      *(float2*)&C[(size_t)r0*ldc + cc]     = make_float2(acc[mf][nf][0], acc[mf][nf][1]);
      *(float2*)&C[(size_t)(r0+8)*ldc + cc] = make_float2(acc[mf][nf][2], acc[mf][nf][3]);
    }
  }
}

// ---------------------------------------------------------------------------
// Kernels
// ---------------------------------------------------------------------------
__global__ void __launch_bounds__(256)
k_prep(const float* __restrict__ x, const float* __restrict__ W)
{
  const size_t nx = (size_t)NB*NCTX*DM/4, nw = (size_t)DM*DM/4;
  for (size_t i = blockIdx.x*256 + threadIdx.x; i < nx + nw; i += (size_t)gridDim.x*256){
    float4 v;
    __nv_bfloat16* hi; __nv_bfloat16* lo; size_t j;
    if (i < nx){ v = ((const float4*)x)[i];      hi = g_xhi; lo = g_xlo; j = i; }
    else       { v = ((const float4*)W)[i - nx]; hi = g_Whi; lo = g_Wlo; j = i - nx; }
    __nv_bfloat16 hx = __float2bfloat16_rn(v.x), hy = __float2bfloat16_rn(v.y);
    __nv_bfloat16 hz = __float2bfloat16_rn(v.z), hw = __float2bfloat16_rn(v.w);
    __nv_bfloat162 h01; h01.x = hx; h01.y = hy;
    __nv_bfloat162 h23; h23.x = hz; h23.y = hw;
    __nv_bfloat162 l01; l01.x = __float2bfloat16_rn(v.x - __bfloat162float(hx));
                        l01.y = __float2bfloat16_rn(v.y - __bfloat162float(hy));
    __nv_bfloat162 l23; l23.x = __float2bfloat16_rn(v.z - __bfloat162float(hz));
                        l23.y = __float2bfloat16_rn(v.w - __bfloat162float(hw));
    ((__nv_bfloat162*)hi)[2*j]     = h01;
    ((__nv_bfloat162*)hi)[2*j + 1] = h23;
    ((__nv_bfloat162*)lo)[2*j]     = l01;
    ((__nv_bfloat162*)lo)[2*j + 1] = l23;
  }
}

__global__ void __launch_bounds__(256, 2)
k_proj()
{ // K = x @ W^T -> Khi/Klo (bf16, K-major) and g_Ktb (fp16, transposed)
  const int n0 = blockIdx.x*128, m0 = blockIdx.y*128;
  bgemm_split(g_xhi, g_xlo, DM, g_Whi, g_Wlo, DM, m0, n0, DM,
    [&](float (&acc)[2][8][4]){
      const int t = threadIdx.x, l = t & 31, w = t >> 5;
      const int wm = w & 3, wn = w >> 2;
      #pragma unroll
      for (int mf = 0; mf < 2; mf++){
        const int r0 = m0 + wm*32 + mf*16 + (l >> 2);
        #pragma unroll
        for (int nf = 0; nf < 8; nf++){
          const int cc = n0 + wn*64 + nf*8 + 2*(l & 3);
          #pragma unroll
          for (int hh = 0; hh < 2; hh++){
            const int r = r0 + hh*8;
            const float v0 = acc[mf][nf][2*hh], v1 = acc[mf][nf][2*hh+1];
            __nv_bfloat16 h0 = __float2bfloat16_rn(v0), h1 = __float2bfloat16_rn(v1);
            __nv_bfloat162 hp; hp.x = h0; hp.y = h1;
            __nv_bfloat162 lp;
            lp.x = __float2bfloat16_rn(v0 - __bfloat162float(h0));
            lp.y = __float2bfloat16_rn(v1 - __bfloat162float(h1));
            const size_t ki = (size_t)r*DM + cc;
            *(__nv_bfloat162*)&g_Khi[ki] = hp;
            *(__nv_bfloat162*)&g_Klo[ki] = lp;
            g_Ktb[(size_t)cc    *LDKT + r] = __float2half_rn(v0);
            g_Ktb[(size_t)(cc+1)*LDKT + r] = __float2half_rn(v1);
          }
        }
      }
    });
}

__global__ void __launch_bounds__(256, 2)
k_scores()
{
  const int b  = blockIdx.z;
  const int n0 = blockIdx.x*128, m0 = blockIdx.y*128;
  if (n0 > m0) return;
  const size_t off = (size_t)b*NCTX*DM;
  float* Sb = g_S + (size_t)b*NCTX*NCTX;
  bgemm_split(g_xhi + off, g_xlo + off, DM, g_Khi + off, g_Klo + off, DM,
    m0, n0, DM,
    [&](float (&acc)[2][8][4]){ epi_store(acc, Sb, NCTX, m0, n0); });
}

// ---------------------------------------------------------------------------
// softmax: single global read; row held in registers (<=16 floats/thread).
// Writes fp16 exp(s-m); g_inv = 1/rowsum; zero-fills P to 128 boundary.
// ---------------------------------------------------------------------------
__device__ __forceinline__ float blk_red(float v, bool is_max)
{
  __shared__ float sm[8];
  const int lane = threadIdx.x & 31, w = threadIdx.x >> 5;
  #pragma unroll
  for (int o = 16; o; o >>= 1){
    float u = __shfl_xor_sync(0xffffffffu, v, o);
    v = is_max ? fmaxf(v, u) : v + u;
  }
  if (lane == 0) sm[w] = v;
  __syncthreads();
  float r = sm[0];
  #pragma unroll
  for (int i = 1; i < 8; i++) r = is_max ? fmaxf(r, sm[i]) : r + sm[i];
  __syncthreads();
  return r;
}

__global__ void __launch_bounds__(256)
k_softmax()
{
  const int row = blockIdx.x;
  const int q   = row & (NCTX - 1);
  const float* p = g_S + (size_t)row * NCTX;
  __half* pb = g_Pb + (size_t)row * NCTX;
  const int len  = q + 1;
  const int len4 = len >> 2;
  const float4* p4 = (const float4*)p;
  __half2* pb2 = (__half2*)pb;

  float4 v[4];
  float tl = 0.f;
  const int tbase = len4 << 2;
  const int tidx  = tbase + threadIdx.x;
  const bool has_tail = (tidx < len);

  float m = -1e30f;
  #pragma unroll
  for (int k = 0; k < 4; k++){
    const int idx = threadIdx.x + (k << 8);
    if (idx < len4){
      v[k] = p4[idx];
      m = fmaxf(m, fmaxf(fmaxf(v[k].x, v[k].y), fmaxf(v[k].z, v[k].w)));
    }
  }
  if (has_tail){ tl = p[tidx]; m = fmaxf(m, tl); }
  m = blk_red(m, true);

  float s = 0.f;
  #pragma unroll
  for (int k = 0; k < 4; k++){
    const int idx = threadIdx.x + (k << 8);
    if (idx < len4){
      float ex = __expf(v[k].x - m), ey = __expf(v[k].y - m);
      float ez = __expf(v[k].z - m), ew = __expf(v[k].w - m);
      s += (ex + ey) + (ez + ew);
      pb2[2*idx]     = __floats2half2_rn(ex, ey);
      pb2[2*idx + 1] = __floats2half2_rn(ez, ew);
    }
  }
  if (has_tail){
    float e = __expf(tl - m);
    s += e;
    pb[tidx] = __float2half_rn(e);
  }
  s = blk_red(s, false);
  if (threadIdx.x == 0) g_inv[row] = 1.f / s;

  const int lenUp = (len + 127) & ~127;
  for (int i = len + threadIdx.x; i < lenUp; i += 256)
    pb[i] = __float2half_rn(0.f);
}

// ---------------------------------------------------------------------------
// out = x + (P @ K) * inv. fp16 single MMA. M_TILE=64, N_TILE=128.
// 256 equal CTAs: pair (i, 63-i) x 4 n-strips. No atomics.
// ---------------------------------------------------------------------------
__global__ void __launch_bounds__(256, 2)
k_out_h(const float* __restrict__ x, float* __restrict__ out)
{
  const int b    = blockIdx.z;
  const int n0   = blockIdx.x*128;      // 4 strips
  const int pair = blockIdx.y;          // 0..31
  const __half* Pb = g_Pb  + (size_t)b*NCTX*NCTX;
  const __half* Bt = g_Ktb + (size_t)b*NCTX;

  #pragma unroll
  for (int s = 0; s < 2; s++){
    const int i  = s ? (63 - pair) : pair;
    const int m0 = i*64;
    hgemm_out(Pb, NCTX, Bt, LDKT, m0, n0, (i + 1)*64,
      [&](float (&acc)[2][4][4]){
        const int t = threadIdx.x, l = t & 31, w = t >> 5;
        const int wm = w & 1, wn = w >> 1;
        #pragma unroll
        for (int mf = 0; mf < 2; mf++){
          const int r0 = m0 + wm*32 + mf*16 + (l >> 2);
          const float inv0 = g_inv[b*NCTX + r0];
          const float inv1 = g_inv[b*NCTX + r0 + 8];
          #pragma unroll
          for (int nf = 0; nf < 4; nf++){
            const int cc = n0 + wn*32 + nf*8 + 2*(l & 3);
            const size_t i0 = (size_t)b*NCTX*DM + (size_t)r0*DM + cc;
            const size_t i1 = i0 + (size_t)8*DM;
            *(float2*)&out[i0] = make_float2(acc[mf][nf][0]*inv0 + x[i0],
                                             acc[mf][nf][1]*inv0 + x[i0+1]);
            *(float2*)&out[i1] = make_float2(acc[mf][nf][2]*inv1 + x[i1],
                                             acc[mf][nf][3]*inv1 + x[i1+1]);
          }
        }
      });
  }
}

// ---------------------------------------------------------------------------
extern "C" void kernel_launch(void* const* d_in, const int* in_sizes, int n_in,
                              void* d_out, int out_size)
{
  const float* x = (const float*)d_in[0];
  const float* W = (const float*)d_in[1];
  float* out = (float*)d_out;

  const int SMEM_BF  = 2 * BT_STAGE;     // 81920
  const int SMEM_OUT = 3 * KST;          // 46080
  cudaFuncSetAttribute(k_proj,   cudaFuncAttributeMaxDynamicSharedMemorySize, SMEM_BF);
  cudaFuncSetAttribute(k_scores, cudaFuncAttributeMaxDynamicSharedMemorySize, SMEM_BF);
  cudaFuncSetAttribute(k_out_h,  cudaFuncAttributeMaxDynamicSharedMemorySize, SMEM_OUT);

  k_prep   <<<1184, 256>>>(x, W);
  k_proj   <<<dim3(4, 64),      256, SMEM_BF>>>();
  k_scores <<<dim3(32, 32, NB), 256, SMEM_BF>>>();
  k_softmax<<<NB * NCTX, 256>>>();
  k_out_h  <<<dim3(4, 32, NB),  256, SMEM_OUT>>>(x, out);
}

// round 16
// speedup vs baseline: 1.1499x; 1.0462x over previous
#include <cuda_runtime.h>
#include <cuda_bf16.h>
#include <cuda_fp16.h>
#include <cstdint>

#define NCTX 4096
#define DM   512
#define NB   2
#define LDKT (NB*NCTX)

// Scratch
__device__ __nv_bfloat16 g_xhi[(size_t)NB*NCTX*DM];
__device__ __nv_bfloat16 g_xlo[(size_t)NB*NCTX*DM];
__device__ __nv_bfloat16 g_Whi[(size_t)DM*DM];
__device__ __nv_bfloat16 g_Wlo[(size_t)DM*DM];
__device__ __nv_bfloat16 g_Khi[(size_t)NB*NCTX*DM];
__device__ __nv_bfloat16 g_Klo[(size_t)NB*NCTX*DM];
__device__ __half        g_Ktb[(size_t)DM*NB*NCTX];   // fp16 K^T
__device__ float         g_S  [(size_t)NB*NCTX*NCTX]; // fp32 scores
__device__ __half        g_Pb [(size_t)NB*NCTX*NCTX]; // fp16 exp(s-m)
__device__ float         g_inv[(size_t)NB*NCTX];      // 1 / rowsum(exp)

// ---------------------------------------------------------------------------
// helpers
// ---------------------------------------------------------------------------
__device__ __forceinline__ uint32_t s2u(const void* p){
  uint32_t a;
  asm("{ .reg .u64 t; cvta.to.shared.u64 t, %1; cvt.u32.u64 %0, t; }" : "=r"(a) : "l"(p));
  return a;
}
__device__ __forceinline__ void ldsm4(uint32_t* r, uint32_t addr){
  asm volatile("ldmatrix.sync.aligned.m8n8.x4.shared.b16 {%0,%1,%2,%3}, [%4];"
    : "=r"(r[0]), "=r"(r[1]), "=r"(r[2]), "=r"(r[3]) : "r"(addr));
}
__device__ __forceinline__ void bmma(float* c, const uint32_t* a, const uint32_t* b){
  asm volatile("mma.sync.aligned.m16n8k16.row.col.f32.bf16.bf16.f32 "
    "{%0,%1,%2,%3}, {%4,%5,%6,%7}, {%8,%9}, {%0,%1,%2,%3};"
    : "+f"(c[0]), "+f"(c[1]), "+f"(c[2]), "+f"(c[3])
    : "r"(a[0]), "r"(a[1]), "r"(a[2]), "r"(a[3]), "r"(b[0]), "r"(b[1]));
}
__device__ __forceinline__ void hmma(float* c, const uint32_t* a, const uint32_t* b){
  asm volatile("mma.sync.aligned.m16n8k16.row.col.f32.f16.f16.f32 "
    "{%0,%1,%2,%3}, {%4,%5,%6,%7}, {%8,%9}, {%0,%1,%2,%3};"
    : "+f"(c[0]), "+f"(c[1]), "+f"(c[2]), "+f"(c[3])
    : "r"(a[0]), "r"(a[1]), "r"(a[2]), "r"(a[3]), "r"(b[0]), "r"(b[1]));
}
__device__ __forceinline__ void cp16(uint32_t d, const void* s){
  asm volatile("cp.async.cg.shared.global [%0], [%1], 16;" :: "r"(d), "l"(s));
}
__device__ __forceinline__ void cp_commit(){
  asm volatile("cp.async.commit_group;" ::: "memory");
}
template<int N> __device__ __forceinline__ void cp_wait(){
  asm volatile("cp.async.wait_group %0;" :: "n"(N) : "memory");
}

// ===========================================================================
// bf16 split (3-MMA) GEMM, 512 threads: C[128 x 256] = A * B^T (hi/lo).
// BK=32, 2 stages, pitch 80 B. 16 warps = 4(M) x 4(N); warp tile 32x64.
// Term-major inner ordering (accumulator reuse distance 8).
// ===========================================================================
#define A_TILE5 10240                       // 128 * 80
#define B_TILE5 20480                       // 256 * 80
#define STAGE5  (2*A_TILE5 + 2*B_TILE5)     // 61440; 2 stages = 122880

template<class EPI>
__device__ __forceinline__ void bgemm512(
    const __nv_bfloat16* __restrict__ Ah, const __nv_bfloat16* __restrict__ Al, int lda,
    const __nv_bfloat16* __restrict__ Bh, const __nv_bfloat16* __restrict__ Bl, int ldb,
    int m0, int n0, int k1, EPI&& epi)
{
  extern __shared__ __align__(16) char sd[];
  const int t = threadIdx.x, l = t & 31, w = t >> 5;
  const int wm = w & 3, wn = w >> 2;
  const uint32_t sb = s2u(sd);

  const int arow = t >> 2, aseg = (t & 3) * 8;
  const uint32_t soA = (uint32_t)arow*80 + (t & 3)*16;
  const __nv_bfloat16* pAh = Ah + (size_t)(m0 + arow)*lda + aseg;
  const __nv_bfloat16* pAl = Al + (size_t)(m0 + arow)*lda + aseg;
  const __nv_bfloat16* pBh = Bh + (size_t)(n0 + arow)*ldb + aseg;
  const __nv_bfloat16* pBl = Bl + (size_t)(n0 + arow)*ldb + aseg;
  const __nv_bfloat16* qBh = Bh + (size_t)(n0 + arow + 128)*ldb + aseg;
  const __nv_bfloat16* qBl = Bl + (size_t)(n0 + arow + 128)*ldb + aseg;
  const uint32_t soB2 = soA + 128*80;

  const int nch = k1 >> 5;
  auto load_stage = [&](int c){
    const int kb = c << 5;
    const uint32_t st = sb + (c & 1)*STAGE5;
    cp16(st + soA,                        pAh + kb);
    cp16(st + soA + A_TILE5,              pAl + kb);
    cp16(st + soA + 2*A_TILE5,            pBh + kb);
    cp16(st + soB2 + 2*A_TILE5,           qBh + kb);
    cp16(st + soA + 2*A_TILE5 + B_TILE5,  pBl + kb);
    cp16(st + soB2 + 2*A_TILE5 + B_TILE5, qBl + kb);
  };
  load_stage(0);
  cp_commit();

  const uint32_t aoff = (uint32_t)(wm*32 + (l & 15))*80 + ((l >> 4) & 1)*16;
  const uint32_t boff = (uint32_t)(wn*64 + (l & 7) + ((l >> 4) & 1)*8)*80
                      + ((l >> 3) & 1)*16;

  float acc[2][8][4] = {};

  for (int c = 0; c < nch; c++){
    cp_wait<0>();
    __syncthreads();
    if (c + 1 < nch) load_stage(c + 1);
    cp_commit();

    const uint32_t base = sb + (c & 1)*STAGE5;
    const uint32_t uAh = base + aoff,               uAl = uAh + A_TILE5;
    const uint32_t uBh = base + 2*A_TILE5 + boff,   uBl = uBh + B_TILE5;

    #pragma unroll
    for (int kf = 0; kf < 2; kf++){
      const uint32_t ko = kf*32;
      uint32_t ah[2][4], al[2][4];
      ldsm4(ah[0], uAh + ko);  ldsm4(ah[1], uAh + ko + 16*80);
      ldsm4(al[0], uAl + ko);  ldsm4(al[1], uAl + ko + 16*80);
      #pragma unroll
      for (int h = 0; h < 2; h++){
        uint32_t bh[2][4], bl[2][4];
        ldsm4(bh[0], uBh + ko + (2*h    )*16*80);
        ldsm4(bh[1], uBh + ko + (2*h + 1)*16*80);
        ldsm4(bl[0], uBl + ko + (2*h    )*16*80);
        ldsm4(bl[1], uBl + ko + (2*h + 1)*16*80);
        #pragma unroll
        for (int j = 0; j < 2; j++)
          #pragma unroll
          for (int mf = 0; mf < 2; mf++){
            bmma(acc[mf][2*(2*h+j)],     ah[mf], bh[j]);
            bmma(acc[mf][2*(2*h+j) + 1], ah[mf], bh[j] + 2);
          }
        #pragma unroll
        for (int j = 0; j < 2; j++)
          #pragma unroll
          for (int mf = 0; mf < 2; mf++){
            bmma(acc[mf][2*(2*h+j)],     ah[mf], bl[j]);
            bmma(acc[mf][2*(2*h+j) + 1], ah[mf], bl[j] + 2);
          }
        #pragma unroll
        for (int j = 0; j < 2; j++)
          #pragma unroll
          for (int mf = 0; mf < 2; mf++){
            bmma(acc[mf][2*(2*h+j)],     al[mf], bh[j]);
            bmma(acc[mf][2*(2*h+j) + 1], al[mf], bh[j] + 2);
          }
      }
    }
  }
  epi(acc);
}

// store epilogue for 512-thread gemm (wn 0..3)
__device__ __forceinline__ void epi_store5(float (&acc)[2][8][4],
                                           float* __restrict__ C, int ldc,
                                           int m0, int n0)
{
  const int t = threadIdx.x, l = t & 31, w = t >> 5;
  const int wm = w & 3, wn = w >> 2;
  #pragma unroll
  for (int mf = 0; mf < 2; mf++){
    const int r0 = m0 + wm*32 + mf*16 + (l >> 2);
    #pragma unroll
    for (int nf = 0; nf < 8; nf++){
      const int cc = n0 + wn*64 + nf*8 + 2*(l & 3);
      *(float2*)&C[(size_t)r0*ldc + cc]     = make_float2(acc[mf][nf][0], acc[mf][nf][1]);
      *(float2*)&C[(size_t)(r0+8)*ldc + cc] = make_float2(acc[mf][nf][2], acc[mf][nf][3]);
    }
  }
}

// ===========================================================================
// fp16 single GEMM, 256 threads: C[64 x 128] = A * B^T. BK=32, 3 stages.
// (R15 proven)
// ===========================================================================
#define KA_T 5120
#define KB_T 10240
#define KST  (KA_T + KB_T)          // 15360; 3 stages = 46080

template<class EPI>
__device__ __forceinline__ void hgemm_out(
    const __half* __restrict__ A, int lda,
    const __half* __restrict__ B, int ldb,
    int m0, int n0, int k1, EPI&& epi)
{
  extern __shared__ __align__(16) char sd[];
  const int t = threadIdx.x, l = t & 31, w = t >> 5;
  const int wm = w & 1, wn = w >> 1;
  const uint32_t sb = s2u(sd);

  const int ar = t >> 2, as = (t & 3) * 8;
  const uint32_t soA = (uint32_t)ar*80 + (t & 3)*16;
  const __half* pA = A + (size_t)(m0 + ar)*lda + as;
  const __half* pB = B + (size_t)(n0 + ar)*ldb + as;

  cp_wait<0>();
  __syncthreads();

  const int nch = k1 >> 5;
  auto load_stage = [&](int c){
    const int kb = c << 5;
    const uint32_t st = sb + (c % 3)*KST;
    cp16(st + soA, pA + kb);
    cp16(st + KA_T + soA,        pB + kb);
    cp16(st + KA_T + soA + KA_T, pB + (size_t)64*ldb + kb);
  };
  load_stage(0); cp_commit();
  if (1 < nch) load_stage(1);
  cp_commit();

  const uint32_t aoff = (uint32_t)(wm*32 + (l & 15))*80 + ((l >> 4) & 1)*16;
  const uint32_t boff = (uint32_t)(wn*32 + (l & 7) + ((l >> 4) & 1)*8)*80
                      + ((l >> 3) & 1)*16;

  float acc[2][4][4] = {};

  for (int c = 0; c < nch; c++){
    cp_wait<1>();
    __syncthreads();
    if (c + 2 < nch) load_stage(c + 2);
    cp_commit();

    const uint32_t base = sb + (c % 3)*KST;
    const uint32_t uA = base + aoff;
    const uint32_t uB = base + KA_T + boff;

    #pragma unroll
    for (int kf = 0; kf < 2; kf++){
      const uint32_t ko = kf*32;
      uint32_t a[2][4];
      ldsm4(a[0], uA + ko);
      ldsm4(a[1], uA + ko + 16*80);
      #pragma unroll
      for (int nf2 = 0; nf2 < 2; nf2++){
        uint32_t b[4];
        ldsm4(b, uB + ko + nf2*16*80);
        #pragma unroll
        for (int mf = 0; mf < 2; mf++){
          hmma(acc[mf][2*nf2],     a[mf], b);
          hmma(acc[mf][2*nf2 + 1], a[mf], b + 2);
        }
      }
    }
  }
  epi(acc);
}

// ---------------------------------------------------------------------------
// Kernels
// ---------------------------------------------------------------------------
__global__ void __launch_bounds__(256)
k_prep(const float* __restrict__ x, const float* __restrict__ W)
{
  const size_t nx = (size_t)NB*NCTX*DM/4, nw = (size_t)DM*DM/4;
  for (size_t i = blockIdx.x*256 + threadIdx.x; i < nx + nw; i += (size_t)gridDim.x*256){
    float4 v;
    __nv_bfloat16* hi; __nv_bfloat16* lo; size_t j;
    if (i < nx){ v = ((const float4*)x)[i];      hi = g_xhi; lo = g_xlo; j = i; }
    else       { v = ((const float4*)W)[i - nx]; hi = g_Whi; lo = g_Wlo; j = i - nx; }
    __nv_bfloat16 hx = __float2bfloat16_rn(v.x), hy = __float2bfloat16_rn(v.y);
    __nv_bfloat16 hz = __float2bfloat16_rn(v.z), hw = __float2bfloat16_rn(v.w);
    __nv_bfloat162 h01; h01.x = hx; h01.y = hy;
    __nv_bfloat162 h23; h23.x = hz; h23.y = hw;
    __nv_bfloat162 l01; l01.x = __float2bfloat16_rn(v.x - __bfloat162float(hx));
                        l01.y = __float2bfloat16_rn(v.y - __bfloat162float(hy));
    __nv_bfloat162 l23; l23.x = __float2bfloat16_rn(v.z - __bfloat162float(hz));
                        l23.y = __float2bfloat16_rn(v.w - __bfloat162float(hw));
    ((__nv_bfloat162*)hi)[2*j]     = h01;
    ((__nv_bfloat162*)hi)[2*j + 1] = h23;
    ((__nv_bfloat162*)lo)[2*j]     = l01;
    ((__nv_bfloat162*)lo)[2*j + 1] = l23;
  }
}

__global__ void __launch_bounds__(512, 1)
k_proj()
{ // K = x @ W^T -> Khi/Klo (bf16, K-major) and g_Ktb (fp16, transposed)
  const int n0 = blockIdx.x*256, m0 = blockIdx.y*128;
  bgemm512(g_xhi, g_xlo, DM, g_Whi, g_Wlo, DM, m0, n0, DM,
    [&](float (&acc)[2][8][4]){
      const int t = threadIdx.x, l = t & 31, w = t >> 5;
      const int wm = w & 3, wn = w >> 2;
      #pragma unroll
      for (int mf = 0; mf < 2; mf++){
        const int r0 = m0 + wm*32 + mf*16 + (l >> 2);
        #pragma unroll
        for (int nf = 0; nf < 8; nf++){
          const int cc = n0 + wn*64 + nf*8 + 2*(l & 3);
          #pragma unroll
          for (int hh = 0; hh < 2; hh++){
            const int r = r0 + hh*8;
            const float v0 = acc[mf][nf][2*hh], v1 = acc[mf][nf][2*hh+1];
            __nv_bfloat16 h0 = __float2bfloat16_rn(v0), h1 = __float2bfloat16_rn(v1);
            __nv_bfloat162 hp; hp.x = h0; hp.y = h1;
            __nv_bfloat162 lp;
            lp.x = __float2bfloat16_rn(v0 - __bfloat162float(h0));
            lp.y = __float2bfloat16_rn(v1 - __bfloat162float(h1));
            const size_t ki = (size_t)r*DM + cc;
            *(__nv_bfloat162*)&g_Khi[ki] = hp;
            *(__nv_bfloat162*)&g_Klo[ki] = lp;
            g_Ktb[(size_t)cc    *LDKT + r] = __float2half_rn(v0);
            g_Ktb[(size_t)(cc+1)*LDKT + r] = __float2half_rn(v1);
          }
        }
      }
    });
}

__global__ void __launch_bounds__(512, 1)
k_scores()
{ // S = x @ K^T, lower-triangular 128x256 tiles (tile needed iff 2j <= i)
  const int b = blockIdx.z;
  const int j = blockIdx.x, i = blockIdx.y;
  if (2*j > i) return;
  const int n0 = j*256, m0 = i*128;
  const size_t off = (size_t)b*NCTX*DM;
  float* Sb = g_S + (size_t)b*NCTX*NCTX;
  bgemm512(g_xhi + off, g_xlo + off, DM, g_Khi + off, g_Klo + off, DM,
    m0, n0, DM,
    [&](float (&acc)[2][8][4]){ epi_store5(acc, Sb, NCTX, m0, n0); });
}

// ---------------------------------------------------------------------------
// softmax: single global read; row held in registers (<=16 floats/thread).
// Writes fp16 exp(s-m); g_inv = 1/rowsum; zero-fills P to 128 boundary.
// ---------------------------------------------------------------------------
__device__ __forceinline__ float blk_red(float v, bool is_max)
{
  __shared__ float sm[8];
  const int lane = threadIdx.x & 31, w = threadIdx.x >> 5;
  #pragma unroll
  for (int o = 16; o; o >>= 1){
    float u = __shfl_xor_sync(0xffffffffu, v, o);
    v = is_max ? fmaxf(v, u) : v + u;
  }
  if (lane == 0) sm[w] = v;
  __syncthreads();
  float r = sm[0];
  #pragma unroll
  for (int i = 1; i < 8; i++) r = is_max ? fmaxf(r, sm[i]) : r + sm[i];
  __syncthreads();
  return r;
}

__global__ void __launch_bounds__(256)
k_softmax()
{
  const int row = blockIdx.x;
  const int q   = row & (NCTX - 1);
  const float* p = g_S + (size_t)row * NCTX;
  __half* pb = g_Pb + (size_t)row * NCTX;
  const int len  = q + 1;
  const int len4 = len >> 2;
  const float4* p4 = (const float4*)p;
  __half2* pb2 = (__half2*)pb;

  float4 v[4];
  float tl = 0.f;
  const int tbase = len4 << 2;
  const int tidx  = tbase + threadIdx.x;
  const bool has_tail = (tidx < len);

  float m = -1e30f;
  #pragma unroll
  for (int k = 0; k < 4; k++){
    const int idx = threadIdx.x + (k << 8);
    if (idx < len4){
      v[k] = p4[idx];
      m = fmaxf(m, fmaxf(fmaxf(v[k].x, v[k].y), fmaxf(v[k].z, v[k].w)));
    }
  }
  if (has_tail){ tl = p[tidx]; m = fmaxf(m, tl); }
  m = blk_red(m, true);

  float s = 0.f;
  #pragma unroll
  for (int k = 0; k < 4; k++){
    const int idx = threadIdx.x + (k << 8);
    if (idx < len4){
      float ex = __expf(v[k].x - m), ey = __expf(v[k].y - m);
      float ez = __expf(v[k].z - m), ew = __expf(v[k].w - m);
      s += (ex + ey) + (ez + ew);
      pb2[2*idx]     = __floats2half2_rn(ex, ey);
      pb2[2*idx + 1] = __floats2half2_rn(ez, ew);
    }
  }
  if (has_tail){
    float e = __expf(tl - m);
    s += e;
    pb[tidx] = __float2half_rn(e);
  }
  s = blk_red(s, false);
  if (threadIdx.x == 0) g_inv[row] = 1.f / s;

  const int lenUp = (len + 127) & ~127;
  for (int i = len + threadIdx.x; i < lenUp; i += 256)
    pb[i] = __float2half_rn(0.f);
}

// ---------------------------------------------------------------------------
// out = x + (P @ K) * inv. fp16 single MMA. M_TILE=64, N_TILE=128.
// 256 equal CTAs: pair (i, 63-i) x 4 n-strips. No atomics.
// ---------------------------------------------------------------------------
__global__ void __launch_bounds__(256, 2)
k_out_h(const float* __restrict__ x, float* __restrict__ out)
{
  const int b    = blockIdx.z;
  const int n0   = blockIdx.x*128;
  const int pair = blockIdx.y;
  const __half* Pb = g_Pb  + (size_t)b*NCTX*NCTX;
  const __half* Bt = g_Ktb + (size_t)b*NCTX;

  #pragma unroll
  for (int s = 0; s < 2; s++){
    const int i  = s ? (63 - pair) : pair;
    const int m0 = i*64;
    hgemm_out(Pb, NCTX, Bt, LDKT, m0, n0, (i + 1)*64,
      [&](float (&acc)[2][4][4]){
        const int t = threadIdx.x, l = t & 31, w = t >> 5;
        const int wm = w & 1, wn = w >> 1;
        #pragma unroll
        for (int mf = 0; mf < 2; mf++){
          const int r0 = m0 + wm*32 + mf*16 + (l >> 2);
          const float inv0 = g_inv[b*NCTX + r0];
          const float inv1 = g_inv[b*NCTX + r0 + 8];
          #pragma unroll
          for (int nf = 0; nf < 4; nf++){
            const int cc = n0 + wn*32 + nf*8 + 2*(l & 3);
            const size_t i0 = (size_t)b*NCTX*DM + (size_t)r0*DM + cc;
            const size_t i1 = i0 + (size_t)8*DM;
            *(float2*)&out[i0] = make_float2(acc[mf][nf][0]*inv0 + x[i0],
                                             acc[mf][nf][1]*inv0 + x[i0+1]);
            *(float2*)&out[i1] = make_float2(acc[mf][nf][2]*inv1 + x[i1],
                                             acc[mf][nf][3]*inv1 + x[i1+1]);
          }
        }
      });
  }
}

// ---------------------------------------------------------------------------
extern "C" void kernel_launch(void* const* d_in, const int* in_sizes, int n_in,
                              void* d_out, int out_size)
{
  const float* x = (const float*)d_in[0];
  const float* W = (const float*)d_in[1];
  float* out = (float*)d_out;

  const int SMEM5   = 2 * STAGE5;      // 122880
  const int SMEM_OUT = 3 * KST;        // 46080
  cudaFuncSetAttribute(k_proj,   cudaFuncAttributeMaxDynamicSharedMemorySize, SMEM5);
  cudaFuncSetAttribute(k_scores, cudaFuncAttributeMaxDynamicSharedMemorySize, SMEM5);
  cudaFuncSetAttribute(k_out_h,  cudaFuncAttributeMaxDynamicSharedMemorySize, SMEM_OUT);

  k_prep   <<<1184, 256>>>(x, W);
  k_proj   <<<dim3(2, 64),      512, SMEM5>>>();
  k_scores <<<dim3(16, 32, NB), 512, SMEM5>>>();
  k_softmax<<<NB * NCTX, 256>>>();
  k_out_h  <<<dim3(4, 32, NB),  256, SMEM_OUT>>>(x, out);
}